// round 16
// baseline (speedup 1.0000x reference)
#include <cuda_runtime.h>
#include <cuda_fp16.h>

// ===== static scratch (allocation-free rule: __device__ globals) =====
#define N_MAX 100352
#define E_MAX 1700032

__device__ int                g_cnt[N_MAX];    // zero at load; self-cleaned by k_a2
__device__ unsigned long long g_pack[N_MAX];   // (cursor<<32)|fixedpoint dinv-sum
__device__ int   g_off[N_MAX + 1];
__device__ int   g_bsum[128];
__device__ int   g_scanflag;                   // publish counter; self-cleaned by k_a2
__device__ float g_dinv[N_MAX];
__device__ __align__(16) int g_src[E_MAX];

__device__ float g_a1[N_MAX];        // P·1
__device__ float g_at[N_MAX];        // dinv * a1
__device__ float g_a2[N_MAX];        // P²·1
__device__ float g_U [96 * 64];      // [W1@W3_top ; W2@W3_bot]
__device__ float g_U2[96 * 64];      // U @ W4
__device__ float g_c4[64];
__device__ float g_e4[64];
__device__ float g_f4[64];

__device__ __align__(16) __half g_T0[(size_t)N_MAX * 64];  // Dinv·([L|C]@U2)
__device__ __align__(16) __half g_T1[(size_t)N_MAX * 64];
__device__ __align__(16) __half g_T2[(size_t)N_MAX * 64];

#define FIXP 16777216.0f   // 2^24

// ===== packed fp32x2 helpers (sm_103a) =====
__device__ __forceinline__ unsigned long long ffma2(unsigned long long a,
                                                    unsigned long long b,
                                                    unsigned long long c) {
    unsigned long long d;
    asm("fma.rn.f32x2 %0, %1, %2, %3;" : "=l"(d) : "l"(a), "l"(b), "l"(c));
    return d;
}
__device__ __forceinline__ unsigned long long pack2(float x) {
    unsigned long long d;
    asm("mov.b64 %0, {%1, %1};" : "=l"(d) : "r"(__float_as_uint(x)));
    return d;
}
__device__ __forceinline__ float2 unpack2(unsigned long long v) {
    unsigned int lo, hi;
    asm("mov.b64 {%0, %1}, %2;" : "=r"(lo), "=r"(hi) : "l"(v));
    return make_float2(__uint_as_float(lo), __uint_as_float(hi));
}

// ============================ graph construction ============================

__global__ void k_hist(const int* __restrict__ col, int E) {
    int e = (blockIdx.x * blockDim.x + threadIdx.x) * 4;
    if (e + 4 <= E) {
        int4 c = *reinterpret_cast<const int4*>(col + e);
        atomicAdd(&g_cnt[c.x], 1);
        atomicAdd(&g_cnt[c.y], 1);
        atomicAdd(&g_cnt[c.z], 1);
        atomicAdd(&g_cnt[c.w], 1);
    } else {
        for (; e < E; e++) atomicAdd(&g_cnt[col[e]], 1);
    }
}

// single-kernel scan: local scan + publish + spin + finalize (98 blocks co-resident)
__global__ void __launch_bounds__(1024) k_scan(int n, int E) {
    __shared__ int s[1024];
    __shared__ int sPre;
    int tid = threadIdx.x;
    int b = blockIdx.x;
    int i = b * 1024 + tid;
    int v = (i < n) ? g_cnt[i] : 0;
    s[tid] = v;
    __syncthreads();
    for (int d = 1; d < 1024; d <<= 1) {
        int t = (tid >= d) ? s[tid - d] : 0;
        __syncthreads();
        s[tid] += t;
        __syncthreads();
    }
    if (tid == 1023) {
        g_bsum[b] = s[1023];
        __threadfence();
        atomicAdd(&g_scanflag, 1);
    }
    if (tid == 0) {
        while (atomicAdd(&g_scanflag, 0) < (int)gridDim.x) { }
        __threadfence();
        int p = 0;
        for (int j = 0; j < b; j++) p += g_bsum[j];
        sPre = p;
    }
    __syncthreads();
    if (i < n) {
        int o = s[tid] - v + sPre;
        g_off[i]  = o;
        g_pack[i] = (unsigned long long)(unsigned)o << 32;
        g_dinv[i] = rsqrtf((float)(v + 1));
    }
    if (i == n) g_off[n] = E;
}

// fill CSR src: ONE packed 64-bit atomic per edge; 2 edges/thread for MLP
__global__ void k_fill(const int* __restrict__ row, const int* __restrict__ col, int E) {
    int e = (blockIdx.x * blockDim.x + threadIdx.x) * 2;
    if (e + 2 <= E) {
        int2 r = *reinterpret_cast<const int2*>(row + e);
        int2 c = *reinterpret_cast<const int2*>(col + e);
        unsigned q0 = (unsigned)__float2uint_rn(g_dinv[r.x] * FIXP);
        unsigned q1 = (unsigned)__float2uint_rn(g_dinv[r.y] * FIXP);
        unsigned long long t0 =
            atomicAdd(&g_pack[c.x], ((unsigned long long)1 << 32) | (unsigned long long)q0);
        unsigned long long t1 =
            atomicAdd(&g_pack[c.y], ((unsigned long long)1 << 32) | (unsigned long long)q1);
        g_src[(int)(t0 >> 32)] = r.x;
        g_src[(int)(t1 >> 32)] = r.y;
    } else {
        for (; e < E; e++) {
            int r = row[e], c = col[e];
            unsigned q = (unsigned)__float2uint_rn(g_dinv[r] * FIXP);
            unsigned long long ret =
                atomicAdd(&g_pack[c], ((unsigned long long)1 << 32) | (unsigned long long)q);
            g_src[(int)(ret >> 32)] = r;
        }
    }
}

// ============================ weight precompute (side stream) ============================
__global__ void __launch_bounds__(256) k_wprep_a(
        const float* __restrict__ W1, const float* __restrict__ W2,
        const float* __restrict__ W3) {
    __shared__ float sB[64 * 64];
    __shared__ float sA[4 * 64];
    int tid = threadIdx.x;
    int k0 = blockIdx.x * 4;
    int half = (k0 >= 64);
    const float* Wsrc = W3 + (size_t)half * 64 * 64;
    for (int i = tid; i < 64 * 64; i += 256) sB[i] = Wsrc[i];
    const float* Arow = half ? (W2 + (size_t)(k0 - 64) * 64) : (W1 + (size_t)k0 * 64);
    sA[tid] = Arow[tid];
    __syncthreads();
    int k = tid >> 6, j = tid & 63;
    float s = 0.f;
#pragma unroll
    for (int m = 0; m < 64; m++) s += sA[k * 64 + m] * sB[m * 64 + j];
    g_U[(k0 + k) * 64 + j] = s;
}

__global__ void __launch_bounds__(256) k_wprep_b(
        const float* __restrict__ W3, const float* __restrict__ W4,
        const float* __restrict__ b1, const float* __restrict__ b2,
        const float* __restrict__ b3, const float* __restrict__ b4) {
    int tid = threadIdx.x;
    int b = blockIdx.x;
    if (b < 24) {
        __shared__ float sB[64 * 64];
        __shared__ float sA[4 * 64];
        int k0 = b * 4;
        for (int i = tid; i < 64 * 64; i += 256) sB[i] = W4[i];
        sA[tid] = g_U[(size_t)k0 * 64 + tid];
        __syncthreads();
        int k = tid >> 6, j = tid & 63;
        float s = 0.f;
#pragma unroll
        for (int m = 0; m < 64; m++) s += sA[k * 64 + m] * sB[m * 64 + j];
        g_U2[(k0 + k) * 64 + j] = s;
    } else {
        __shared__ float c3[64];
        int j = tid & 63;
        if (tid < 64) {
            float s = 0.f;
            for (int m = 0; m < 128; m++)
                s += ((m < 64) ? b1[m] : b2[m - 64]) * W3[m * 64 + j];
            c3[j] = s;
        }
        __syncthreads();
        if (tid < 64) {
            float s = 0.f, t = 0.f;
            for (int m = 0; m < 64; m++) {
                s += c3[m] * W4[m * 64 + j];
                t += b3[m] * W4[m * 64 + j];
            }
            g_c4[j] = s; g_e4[j] = t; g_f4[j] = b4[j];
        }
    }
}

// ============================ gemm0s: T0 = Dinv·([L|C]@U2) ============================
__global__ void __launch_bounds__(256) k_gemm0s(const float* __restrict__ latent,
                                                const float* __restrict__ cond, int n) {
    __shared__ __align__(16) float sW[96 * 64];
    for (int i = threadIdx.x; i < 96 * 64; i += blockDim.x) sW[i] = g_U2[i];
    __syncthreads();
    int node = blockIdx.x * blockDim.x + threadIdx.x;
    if (node >= n) return;

    unsigned long long acc[32];
#pragma unroll
    for (int j = 0; j < 32; j++) acc[j] = 0ull;

    const float* pL = latent + (size_t)node * 64;
    const float* pC = cond   + (size_t)node * 32;
#pragma unroll 2
    for (int k = 0; k < 96; k += 4) {
        float4 av = (k < 64) ? *reinterpret_cast<const float4*>(pL + k)
                             : *reinterpret_cast<const float4*>(pC + (k - 64));
        unsigned long long p0 = pack2(av.x), p1 = pack2(av.y);
        unsigned long long p2 = pack2(av.z), p3 = pack2(av.w);
        const ulonglong2* w0 = reinterpret_cast<const ulonglong2*>(sW + (k + 0) * 64);
        const ulonglong2* w1 = reinterpret_cast<const ulonglong2*>(sW + (k + 1) * 64);
        const ulonglong2* w2 = reinterpret_cast<const ulonglong2*>(sW + (k + 2) * 64);
        const ulonglong2* w3 = reinterpret_cast<const ulonglong2*>(sW + (k + 3) * 64);
#pragma unroll
        for (int j = 0; j < 16; j++) {
            ulonglong2 q;
            q = w0[j]; acc[2*j] = ffma2(p0, q.x, acc[2*j]); acc[2*j+1] = ffma2(p0, q.y, acc[2*j+1]);
            q = w1[j]; acc[2*j] = ffma2(p1, q.x, acc[2*j]); acc[2*j+1] = ffma2(p1, q.y, acc[2*j+1]);
            q = w2[j]; acc[2*j] = ffma2(p2, q.x, acc[2*j]); acc[2*j+1] = ffma2(p2, q.y, acc[2*j+1]);
            q = w3[j]; acc[2*j] = ffma2(p3, q.x, acc[2*j]); acc[2*j+1] = ffma2(p3, q.y, acc[2*j+1]);
        }
    }

    float dn = g_dinv[node];
    __half* yp = g_T0 + (size_t)node * 64;
#pragma unroll
    for (int j = 0; j < 8; j++) {
        float2 f0 = unpack2(acc[4*j+0]);
        float2 f1 = unpack2(acc[4*j+1]);
        float2 f2 = unpack2(acc[4*j+2]);
        float2 f3 = unpack2(acc[4*j+3]);
        __half2 h0 = __floats2half2_rn(f0.x * dn, f0.y * dn);
        __half2 h1 = __floats2half2_rn(f1.x * dn, f1.y * dn);
        __half2 h2 = __floats2half2_rn(f2.x * dn, f2.y * dn);
        __half2 h3 = __floats2half2_rn(f3.x * dn, f3.y * dn);
        uint4 u = make_uint4(*reinterpret_cast<unsigned*>(&h0), *reinterpret_cast<unsigned*>(&h1),
                             *reinterpret_cast<unsigned*>(&h2), *reinterpret_cast<unsigned*>(&h3));
        *reinterpret_cast<uint4*>(yp + 8 * j) = u;
    }
}

// a2 = P·a1 (side stream, overlaps agg2); self-cleans g_cnt + scanflag
__global__ void k_a2(int n) {
    int wid  = (blockIdx.x * blockDim.x + threadIdx.x) >> 5;
    int lane = threadIdx.x & 31;
    if (wid >= n) return;
    int beg = g_off[wid], end = g_off[wid + 1];
    float acc = 0.f;
    for (int e = beg + lane; e < end; e += 32) acc += g_at[g_src[e]];
    for (int d = 16; d; d >>= 1) acc += __shfl_down_sync(0xffffffffu, acc, d);
    if (lane == 0) g_a2[wid] = g_dinv[wid] * (acc + g_at[wid]);
    if (lane == 1) g_cnt[wid] = 0;
    if (lane == 2 && wid == 0) g_scanflag = 0;
}

// ============================ weightless aggregation ============================
// int4-vectorized src loads (peel to 4-alignment), 512-thread blocks.
// MODE 0: fp16 out (dinv²);  MODE 1: FINAL — fp32 out = dinv·G + a2·c4 + a1·e4 + f4
template <int MODE, bool FIRST>
__global__ void __launch_bounds__(512) k_aggp(const __half* __restrict__ X,
                                              void* __restrict__ Yv, int n) {
    int wid  = (blockIdx.x * blockDim.x + threadIdx.x) >> 5;
    int lane = threadIdx.x & 31;
    if (wid >= n) return;

    const int f0 = lane * 2;
    int e = g_off[wid];
    const int end = g_off[wid + 1];
    float a0 = 0.f, a1v = 0.f;

#define GATH(SRC) { __half2 h = *reinterpret_cast<const __half2*>(X + (size_t)(SRC) * 64 + f0); \
                    float2 f = __half22float2(h); a0 += f.x; a1v += f.y; }

    // peel to int4 alignment (node-uniform, <=3 iterations)
    while ((e & 3) && e < end) { int s = g_src[e]; GATH(s) ++e; }
    // main body: 8 edges per iter, src via 2x LDG.128
    for (; e + 8 <= end; e += 8) {
        int4 sa = *reinterpret_cast<const int4*>(g_src + e);
        int4 sb = *reinterpret_cast<const int4*>(g_src + e + 4);
        GATH(sa.x) GATH(sa.y) GATH(sa.z) GATH(sa.w)
        GATH(sb.x) GATH(sb.y) GATH(sb.z) GATH(sb.w)
    }
    if (e + 4 <= end) {
        int4 sa = *reinterpret_cast<const int4*>(g_src + e);
        GATH(sa.x) GATH(sa.y) GATH(sa.z) GATH(sa.w)
        e += 4;
    }
#undef GATH
    {   // predicated tail: rem (0..3) edges + self, always 4 slots
        const int rem = end - e;
        int   idx[4];
        float wgt[4];
#pragma unroll
        for (int k = 0; k < 4; k++) {
            idx[k] = (k < rem) ? g_src[e + k] : wid;
            wgt[k] = (k <= rem) ? 1.f : 0.f;
        }
#pragma unroll
        for (int k = 0; k < 4; k++) {
            __half2 h = *reinterpret_cast<const __half2*>(X + (size_t)idx[k] * 64 + f0);
            float2 f = __half22float2(h);
            a0  += wgt[k] * f.x;
            a1v += wgt[k] * f.y;
        }
    }

    float dn = g_dinv[wid];
    if (FIRST && lane == 0) {
        unsigned low = (unsigned)g_pack[wid];
        float a1 = dn * ((float)low * (1.0f / FIXP) + dn);
        g_a1[wid] = a1;
        g_at[wid] = dn * a1;
    }
    if (MODE == 0) {
        float s = dn * dn;
        __half2 h = __floats2half2_rn(a0 * s, a1v * s);
        *reinterpret_cast<__half2*>((__half*)Yv + (size_t)wid * 64 + f0) = h;
    } else {
        float av1 = g_a1[wid], av2 = g_a2[wid];
        float2 c4v = *reinterpret_cast<const float2*>(g_c4 + f0);
        float2 e4v = *reinterpret_cast<const float2*>(g_e4 + f0);
        float2 f4v = *reinterpret_cast<const float2*>(g_f4 + f0);
        float2 o;
        o.x = a0  * dn + av2 * c4v.x + av1 * e4v.x + f4v.x;
        o.y = a1v * dn + av2 * c4v.y + av1 * e4v.y + f4v.y;
        *reinterpret_cast<float2*>((float*)Yv + (size_t)wid * 64 + f0) = o;
    }
}

// ============================ launch ============================

extern "C" void kernel_launch(void* const* d_in, const int* in_sizes, int n_in,
                              void* d_out, int out_size) {
    const float* latent = (const float*)d_in[0];
    const float* cond   = (const float*)d_in[1];
    const int*   edge   = (const int*)  d_in[2];
    const float* W1 = (const float*)d_in[3];
    const float* b1 = (const float*)d_in[4];
    const float* W2 = (const float*)d_in[5];
    const float* b2 = (const float*)d_in[6];
    const float* W3 = (const float*)d_in[7];
    const float* b3 = (const float*)d_in[8];
    const float* W4 = (const float*)d_in[9];
    const float* b4 = (const float*)d_in[10];

    const int n = in_sizes[0] / 64;      // 100000
    const int E = in_sizes[2] / 2;       // 1600000
    const int* row = edge;
    const int* col = edge + E;

    static __half *pT0 = nullptr, *pT1 = nullptr, *pT2 = nullptr;
    static cudaStream_t sB = nullptr;
    static cudaEvent_t ev0 = nullptr, evAdd = nullptr, evG0 = nullptr,
                       evAgg1 = nullptr, evA2 = nullptr;
    if (!pT0) {
        cudaGetSymbolAddress((void**)&pT0, g_T0);
        cudaGetSymbolAddress((void**)&pT1, g_T1);
        cudaGetSymbolAddress((void**)&pT2, g_T2);
        cudaStreamCreateWithFlags(&sB, cudaStreamNonBlocking);
        cudaEventCreateWithFlags(&ev0,    cudaEventDisableTiming);
        cudaEventCreateWithFlags(&evAdd,  cudaEventDisableTiming);
        cudaEventCreateWithFlags(&evG0,   cudaEventDisableTiming);
        cudaEventCreateWithFlags(&evAgg1, cudaEventDisableTiming);
        cudaEventCreateWithFlags(&evA2,   cudaEventDisableTiming);
    }

    const int TB  = 256;
    const int TBW = 512;                            // agg block size
    const int gN  = (n + TB - 1) / TB;
    const int gE2 = ((E + 1) / 2 + TB - 1) / TB;
    const int gE4 = ((E + 3) / 4 + TB - 1) / TB;
    const int nbS = (n + 1023) / 1024;              // 98 co-resident blocks
    const int gW  = (n + 15) / 16;                  // 16 warps/block, warp per node
    const int gWa = (n + 7) / 8;                    // k_a2: 8 warps/block of 256

    // ---- fork: side stream B computes weights ----
    cudaEventRecord(ev0, 0);
    cudaStreamWaitEvent(sB, ev0, 0);
    k_wprep_a<<<24, 256, 0, sB>>>(W1, W2, W3);
    k_wprep_b<<<25, 256, 0, sB>>>(W3, W4, b1, b2, b3, b4);

    // ---- main stream: hist + fused scan ----
    k_hist<<<gE4, TB>>>(col, E);
    k_scan<<<nbS, 1024>>>(n, E);
    cudaEventRecord(evAdd, 0);
    k_fill<<<gE2, TB>>>(row, col, E);

    // ---- side stream: gemm0s (needs dinv), overlaps fill ----
    cudaStreamWaitEvent(sB, evAdd, 0);
    k_gemm0s<<<gN, TB, 0, sB>>>(latent, cond, n);
    cudaEventRecord(evG0, sB);

    // ---- main stream: agg1 (finalizes a1/at), agg2 ----
    cudaStreamWaitEvent(0, evG0, 0);
    k_aggp<0, true ><<<gW, TBW>>>(pT0, pT1, n);
    cudaEventRecord(evAgg1, 0);
    k_aggp<0, false><<<gW, TBW>>>(pT1, pT2, n);

    // ---- side stream: a2, overlaps agg2 ----
    cudaStreamWaitEvent(sB, evAgg1, 0);
    k_a2<<<gWa, TB, 0, sB>>>(n);
    cudaEventRecord(evA2, sB);

    // ---- final agg writes out ----
    cudaStreamWaitEvent(0, evA2, 0);
    k_aggp<1, false><<<gW, TBW>>>(pT2, (float*)d_out, n);
}